// round 14
// baseline (speedup 1.0000x reference)
#include <cuda_runtime.h>
#include <cuda_fp16.h>
#include <cstdint>

#define B_     4096
#define N_IN   512
#define H1     1536
#define H2     1536
#define N_OUT  512
#define NODES  3584
#define CAP    128            // bucket capacity per dst (Poisson(32), max ~66)
#define TBLOCKS 2048          // transpose blocks in setup kernel
#define NITEMS 3584           // 1536 + 1536 + 512 work items
#define NPERS  1184           // persistent CTAs (148 SMs x up to 8)

typedef unsigned long long u64;

// ---------------- static device scratch (no allocations) ----------------
__device__ __align__(16) __half g_nvTh[NODES * B_];   // 29.4 MB node values fp16
__device__ __align__(16) __half g_outTh[N_OUT * B_];  //  4.2 MB lvl3 result fp16
__device__ int          g_cnt[NODES];                 // zeroed by transpose_out
__device__ unsigned int g_flag[NODES];                // row-ready flags (zeroed by transpose_out)
__device__ unsigned int g_qhead;                      // work-queue head (zeroed by transpose_out)
__device__ __align__(16) int2 g_bpack[NODES * CAP];   // (src, w-bits); slots >= cnt stay 0

// ---------------- packed f32x2 helpers ----------------
__device__ __forceinline__ u64 pack2(float x, float y) {
    u64 r; asm("mov.b64 %0, {%1, %2};" : "=l"(r) : "f"(x), "f"(y)); return r;
}
__device__ __forceinline__ float2 unpack2(u64 v) {
    float2 f; asm("mov.b64 {%0, %1}, %2;" : "=f"(f.x), "=f"(f.y) : "l"(v)); return f;
}
__device__ __forceinline__ void ffma2(u64& acc, u64 a, u64 b) {
    asm("fma.rn.f32x2 %0, %1, %2, %0;" : "+l"(acc) : "l"(a), "l"(b));
}
__device__ __forceinline__ u64 cvt2(uint32_t h2) {
    float2 f = __half22float2(*reinterpret_cast<const __half2*>(&h2));
    return pack2(f.x, f.y);
}

// ---------------- fused setup: x transpose -> fp16 nvT  +  bucket build ----
__global__ void setup_kernel(const float* __restrict__ x,
                             const int* __restrict__ src0, const int* __restrict__ dst0,
                             const float* __restrict__ w0, int E1,
                             const int* __restrict__ src1, const int* __restrict__ dst1,
                             const float* __restrict__ w1, int E2,
                             const int* __restrict__ src2, const int* __restrict__ dst2,
                             const float* __restrict__ w2, int E3) {
    const int tid = threadIdx.x;
    if (blockIdx.x < TBLOCKS) {
        __shared__ float tile[32][33];
        const int bx = (blockIdx.x & 15) * 32;   // node dim
        const int by = (blockIdx.x >> 4) * 32;   // batch dim
        const int tx = tid & 31, ty = tid >> 5;  // 32 x 8
#pragma unroll
        for (int i = 0; i < 32; i += 8)
            tile[ty + i][tx] = x[(size_t)(by + ty + i) * N_IN + bx + tx];
        __syncthreads();
#pragma unroll
        for (int i = 0; i < 32; i += 8)
            g_nvTh[(size_t)(bx + ty + i) * B_ + by + tx] = __float2half(tile[tx][ty + i]);
        return;
    }
    // ---- bucket part: 1 edge per thread (max atomic parallelism) ----
    int i = (blockIdx.x - TBLOCKS) * 256 + tid;
    const int Etot = E1 + E2 + E3;
    if (i >= Etot) return;
    int s, d; float wv;
    if (i < E1)           { s = src0[i];           d = dst0[i];                wv = w0[i]; }
    else if (i < E1 + E2) { int j = i - E1;        s = src1[j]; d = H1 + dst1[j];      wv = w1[j]; }
    else                  { int j = i - E1 - E2;   s = src2[j]; d = H1 + H2 + dst2[j]; wv = w2[j]; }
    int c = atomicAdd(&g_cnt[d], 1);
    if (c < CAP)
        g_bpack[(size_t)d * CAP + c] = make_int2(s, __float_as_int(wv));
}

// ---------------- output transpose (fp16->fp32) + state reset ----------------
__global__ void transpose_out_kernel(float* __restrict__ out) {
    if (blockIdx.x == 0 && blockIdx.y == 0) {
        for (int i = threadIdx.y * 32 + threadIdx.x; i < NODES; i += 256) {
            g_cnt[i]  = 0;
            g_flag[i] = 0;
        }
        if (threadIdx.x == 0 && threadIdx.y == 0) g_qhead = 0;
    }
    __shared__ float tile[32][33];
    const int bd = blockIdx.x * 32;
    const int bb = blockIdx.y * 32;
    const int tx = threadIdx.x, ty = threadIdx.y;
#pragma unroll
    for (int i = 0; i < 32; i += 8)
        tile[ty + i][tx] = __half2float(g_outTh[(size_t)(bd + ty + i) * B_ + bb + tx]);
    __syncthreads();
#pragma unroll
    for (int i = 0; i < 32; i += 8)
        out[(size_t)(bb + ty + i) * N_OUT + bd + tx] = tile[tx][ty + i];
}

// ---------------- per-dst compute (R13-proven NSTRIP=2 body) ----------------
__device__ __forceinline__ void strip_fma(u64* a, u64 W, uint4 v) {
    ffma2(a[0], W, cvt2(v.x));
    ffma2(a[1], W, cvt2(v.y));
    ffma2(a[2], W, cvt2(v.z));
    ffma2(a[3], W, cvt2(v.w));
}

__device__ __forceinline__ void compute_dst(int ci, __half* __restrict__ orow, int t) {
    int cnt = g_cnt[ci];
    if (cnt > CAP) cnt = CAP;
    const int2* bp = g_bpack + (size_t)ci * CAP;
    const int c0 = t * 8;
    const __half* __restrict__ nvTh = g_nvTh;

    u64 acc[2][4];
#pragma unroll
    for (int s = 0; s < 2; s++)
#pragma unroll
        for (int j = 0; j < 4; j++) acc[s][j] = 0;

    int e = 0;
    for (; e + 4 <= cnt; e += 4) {
        int4 m0 = *reinterpret_cast<const int4*>(bp + e);
        int4 m1 = *reinterpret_cast<const int4*>(bp + e + 2);
        const __half* r0 = nvTh + (size_t)m0.x * B_ + c0;
        const __half* r1 = nvTh + (size_t)m0.z * B_ + c0;
        const __half* r2 = nvTh + (size_t)m1.x * B_ + c0;
        const __half* r3 = nvTh + (size_t)m1.z * B_ + c0;
        uint4 v[4][2];
#pragma unroll
        for (int s = 0; s < 2; s++) {
            v[0][s] = *reinterpret_cast<const uint4*>(r0 + s * 2048);
            v[1][s] = *reinterpret_cast<const uint4*>(r1 + s * 2048);
            v[2][s] = *reinterpret_cast<const uint4*>(r2 + s * 2048);
            v[3][s] = *reinterpret_cast<const uint4*>(r3 + s * 2048);
        }
        u64 W0 = pack2(__int_as_float(m0.y), __int_as_float(m0.y));
        u64 W1 = pack2(__int_as_float(m0.w), __int_as_float(m0.w));
        u64 W2 = pack2(__int_as_float(m1.y), __int_as_float(m1.y));
        u64 W3 = pack2(__int_as_float(m1.w), __int_as_float(m1.w));
#pragma unroll
        for (int s = 0; s < 2; s++) {
            strip_fma(acc[s], W0, v[0][s]);
            strip_fma(acc[s], W1, v[1][s]);
            strip_fma(acc[s], W2, v[2][s]);
            strip_fma(acc[s], W3, v[3][s]);
        }
    }
    for (; e < cnt; e++) {
        int2 ep = bp[e];
        const __half* r0 = nvTh + (size_t)ep.x * B_ + c0;
        u64 W0 = pack2(__int_as_float(ep.y), __int_as_float(ep.y));
#pragma unroll
        for (int s = 0; s < 2; s++) {
            uint4 v0 = *reinterpret_cast<const uint4*>(r0 + s * 2048);
            strip_fma(acc[s], W0, v0);
        }
    }

#pragma unroll
    for (int s = 0; s < 2; s++) {
        float r[8];
#pragma unroll
        for (int j = 0; j < 4; j++) {
            float2 f = unpack2(acc[s][j]);
            r[2 * j]     = fmaxf(f.x, 0.f);
            r[2 * j + 1] = fmaxf(f.y, 0.f);
        }
        uint4 o; __half2 h;
        h = __floats2half2_rn(r[0], r[1]); o.x = *reinterpret_cast<uint32_t*>(&h);
        h = __floats2half2_rn(r[2], r[3]); o.y = *reinterpret_cast<uint32_t*>(&h);
        h = __floats2half2_rn(r[4], r[5]); o.z = *reinterpret_cast<uint32_t*>(&h);
        h = __floats2half2_rn(r[6], r[7]); o.w = *reinterpret_cast<uint32_t*>(&h);
        *reinterpret_cast<uint4*>(orow + c0 + s * 2048) = o;
    }
}

// ---------------- persistent work-queue kernel ----------------
// Items 0..1535: lvl1 dst (out row 512+d).  1536..3071: lvl2 dst (row 2048+d,
// waits on src flags).  3072..3583: lvl3 dst (g_outTh row d, waits).
// Queue order guarantees producers of any popped item are already resident.
__global__ void __launch_bounds__(256)
persist_kernel() {
    __shared__ int s_item;
    const int t = threadIdx.x;

    for (;;) {
        if (t == 0) s_item = (int)atomicAdd(&g_qhead, 1u);
        __syncthreads();
        const int item = s_item;
        __syncthreads();
        if (item >= NITEMS) return;

        int ci; __half* orow; bool produce;
        if (item < H1) {
            ci = item;                     orow = g_nvTh + (size_t)(N_IN + item) * B_;      produce = true;
        } else if (item < H1 + H2) {
            int d = item - H1;
            ci = H1 + d;                   orow = g_nvTh + (size_t)(N_IN + H1 + d) * B_;    produce = true;
        } else {
            int d = item - H1 - H2;
            ci = H1 + H2 + d;              orow = g_outTh + (size_t)d * B_;                 produce = false;
        }

        // ---- wait for source rows (levels 2 and 3 only) ----
        if (item >= H1) {
            int cnt = g_cnt[ci];
            if (cnt > CAP) cnt = CAP;
            if (t < cnt) {
                int s = g_bpack[(size_t)ci * CAP + t].x;
                if (s >= N_IN) {
                    unsigned f;
                    for (;;) {
                        asm volatile("ld.acquire.gpu.global.u32 %0, [%1];"
                                     : "=r"(f) : "l"(g_flag + s) : "memory");
                        if (f) break;
                        __nanosleep(64);
                    }
                }
            }
            __syncthreads();
        }

        // ---- compute + store ----
        compute_dst(ci, orow, t);

        // ---- publish (levels 1 and 2) ----
        if (produce) {
            __threadfence();
            __syncthreads();
            if (t == 0) {
                int node = (item < H1) ? (N_IN + item) : (N_IN + H1 + (item - H1));
                asm volatile("st.release.gpu.global.u32 [%0], %1;"
                             :: "l"(g_flag + node), "r"(1u) : "memory");
            }
        }
    }
}

// ---------------- launch ----------------
extern "C" void kernel_launch(void* const* d_in, const int* in_sizes, int n_in,
                              void* d_out, int out_size) {
    const float* x    = (const float*)d_in[0];
    const int*   src0 = (const int*)  d_in[1];
    const int*   dst0 = (const int*)  d_in[2];
    const float* w0   = (const float*)d_in[3];
    const int*   src1 = (const int*)  d_in[4];
    const int*   dst1 = (const int*)  d_in[5];
    const float* w1   = (const float*)d_in[6];
    const int*   src2 = (const int*)  d_in[7];
    const int*   dst2 = (const int*)  d_in[8];
    const float* w2   = (const float*)d_in[9];
    float* out = (float*)d_out;

    const int E1 = in_sizes[1], E2 = in_sizes[4], E3 = in_sizes[7];
    const int Etot = E1 + E2 + E3;

    // 1) fused setup: transpose x (fp32->fp16) + build edge buckets
    {
        int bucketBlocks = (Etot + 255) / 256;   // 1 edge/thread
        setup_kernel<<<TBLOCKS + bucketBlocks, 256>>>(
            x, src0, dst0, w0, E1, src1, dst1, w1, E2, src2, dst2, w2, E3);
    }

    // 2) all three levels in one persistent work-queue kernel
    persist_kernel<<<NPERS, 256>>>();

    // 3) transpose fp16 result to fp32 [B, N_OUT] (+ reset cnt/flags/qhead)
    transpose_out_kernel<<<dim3(N_OUT / 32, B_ / 32), dim3(32, 8)>>>(out);
}

// round 15
// speedup vs baseline: 1.1054x; 1.1054x over previous
#include <cuda_runtime.h>
#include <cuda_fp16.h>
#include <cstdint>

#define B_     4096
#define N_IN   512
#define H1     1536
#define H2     1536
#define N_OUT  512
#define NODES  3584          // N_IN + H1 + H2
#define CAP    128           // bucket capacity per dst (Poisson(32), max ~66)
#define TBLOCKS 512          // 8 x 64 transpose tiles (64 nodes x 64 batch)

typedef unsigned long long u64;

// ---------------- static device scratch (no allocations) ----------------
__device__ __align__(16) __half g_nvTh[NODES * B_];      // 29.4 MB node values, fp16
__device__ __align__(16) __half g_outTh[N_OUT * B_];     //  4.2 MB lvl3 result, fp16
__device__ int  g_cnt[NODES];        // zero at load; re-zeroed by transpose_out
__device__ __align__(16) int2 g_bpack[NODES * CAP];      // (src, w-bits); slots >= cnt stay 0

// ---------------- packed f32x2 helpers ----------------
__device__ __forceinline__ u64 pack2(float x, float y) {
    u64 r; asm("mov.b64 %0, {%1, %2};" : "=l"(r) : "f"(x), "f"(y)); return r;
}
__device__ __forceinline__ float2 unpack2(u64 v) {
    float2 f; asm("mov.b64 {%0, %1}, %2;" : "=f"(f.x), "=f"(f.y) : "l"(v)); return f;
}
__device__ __forceinline__ void ffma2(u64& acc, u64 a, u64 b) {
    asm("fma.rn.f32x2 %0, %1, %2, %0;" : "+l"(acc) : "l"(a), "l"(b));
}
__device__ __forceinline__ u64 cvt2(uint32_t h2) {
    float2 f = __half22float2(*reinterpret_cast<const __half2*>(&h2));
    return pack2(f.x, f.y);
}
// value-row load with L1 retention bias
__device__ __forceinline__ uint4 ldg_el(const __half* p) {
    uint4 v;
    asm volatile("ld.global.nc.L1::evict_last.v4.u32 {%0,%1,%2,%3}, [%4];"
                 : "=r"(v.x), "=r"(v.y), "=r"(v.z), "=r"(v.w)
                 : "l"(__cvta_generic_to_global(p)));
    return v;
}

// ---------------- fused setup: transpose x -> fp16 nvT  +  bucket build ----
// Blocks [0, TBLOCKS): 64x64 transpose tiles, float4 in / uint4 out.
// Blocks [TBLOCKS, ...): bucket build, 2 edges per thread.
__global__ void setup_kernel(const float* __restrict__ x,
                             const int* __restrict__ src0, const int* __restrict__ dst0,
                             const float* __restrict__ w0, int E1,
                             const int* __restrict__ src1, const int* __restrict__ dst1,
                             const float* __restrict__ w1, int E2,
                             const int* __restrict__ src2, const int* __restrict__ dst2,
                             const float* __restrict__ w2, int E3) {
    const int tid = threadIdx.x;
    if (blockIdx.x < TBLOCKS) {
        __shared__ float tile[64][65];
        const int bx = (blockIdx.x & 7) * 64;    // node dim (512/64 = 8)
        const int by = (blockIdx.x >> 3) * 64;   // batch dim (4096/64 = 64)
        // load: 64 batch-rows x 16 float4 = 1024 float4, 4 per thread, coalesced
#pragma unroll
        for (int l = 0; l < 4; l++) {
            int i = tid + l * 256;
            int b = i >> 4, c4 = i & 15;
            float4 v = *reinterpret_cast<const float4*>(x + (size_t)(by + b) * N_IN + bx + c4 * 4);
            tile[b][c4 * 4 + 0] = v.x;
            tile[b][c4 * 4 + 1] = v.y;
            tile[b][c4 * 4 + 2] = v.z;
            tile[b][c4 * 4 + 3] = v.w;
        }
        __syncthreads();
        // store: 64 node-rows x 8 batch-groups (8 cols) = 512 uint4, 2 per thread
#pragma unroll
        for (int l = 0; l < 2; l++) {
            int i = tid + l * 256;
            int n = i >> 3, g = i & 7;
            uint4 o; __half2 h;
            h = __floats2half2_rn(tile[g * 8 + 0][n], tile[g * 8 + 1][n]);
            o.x = *reinterpret_cast<uint32_t*>(&h);
            h = __floats2half2_rn(tile[g * 8 + 2][n], tile[g * 8 + 3][n]);
            o.y = *reinterpret_cast<uint32_t*>(&h);
            h = __floats2half2_rn(tile[g * 8 + 4][n], tile[g * 8 + 5][n]);
            o.z = *reinterpret_cast<uint32_t*>(&h);
            h = __floats2half2_rn(tile[g * 8 + 6][n], tile[g * 8 + 7][n]);
            o.w = *reinterpret_cast<uint32_t*>(&h);
            *reinterpret_cast<uint4*>(g_nvTh + (size_t)(bx + n) * B_ + by + g * 8) = o;
        }
        return;
    }
    // ---- bucket part: 2 consecutive edges per thread ----
    int i0 = ((blockIdx.x - TBLOCKS) * 256 + tid) * 2;
    const int Etot = E1 + E2 + E3;
    if (i0 >= Etot) return;
    const int *sp, *dp; const float* wp; int dbase, j0;
    if (i0 < E1)           { sp = src0; dp = dst0; wp = w0; dbase = 0;       j0 = i0; }
    else if (i0 < E1 + E2) { sp = src1; dp = dst1; wp = w1; dbase = H1;      j0 = i0 - E1; }
    else                   { sp = src2; dp = dst2; wp = w2; dbase = H1 + H2; j0 = i0 - E1 - E2; }
    int2   s = *reinterpret_cast<const int2*>(sp + j0);
    int2   d = *reinterpret_cast<const int2*>(dp + j0);
    float2 w = *reinterpret_cast<const float2*>(wp + j0);
    {
        int c = atomicAdd(&g_cnt[dbase + d.x], 1);
        if (c < CAP) g_bpack[(size_t)(dbase + d.x) * CAP + c] = make_int2(s.x, __float_as_int(w.x));
    }
    {
        int c = atomicAdd(&g_cnt[dbase + d.y], 1);
        if (c < CAP) g_bpack[(size_t)(dbase + d.y) * CAP + c] = make_int2(s.y, __float_as_int(w.y));
    }
}

// ---------------- output transpose (fp16 -> fp32) + cnt reset ----------------
__global__ void transpose_out_kernel(float* __restrict__ out) {
    if (blockIdx.x == 0 && blockIdx.y == 0) {
        for (int i = threadIdx.y * 32 + threadIdx.x; i < NODES; i += 256)
            g_cnt[i] = 0;
    }
    __shared__ float tile[32][33];
    const int bd = blockIdx.x * 32;
    const int bb = blockIdx.y * 32;
    const int tx = threadIdx.x, ty = threadIdx.y;
#pragma unroll
    for (int i = 0; i < 32; i += 8)
        tile[ty + i][tx] = __half2float(g_outTh[(size_t)(bd + ty + i) * B_ + bb + tx]);
    __syncthreads();
#pragma unroll
    for (int i = 0; i < 32; i += 8)
        out[(size_t)(bb + ty + i) * N_OUT + bd + tx] = tile[tx][ty + i];
}

// ---------------- sparse level kernel (R13 shape + evict_last loads) ----------------
__device__ __forceinline__ void strip_fma(u64* a, u64 W, uint4 v) {
    ffma2(a[0], W, cvt2(v.x));
    ffma2(a[1], W, cvt2(v.y));
    ffma2(a[2], W, cvt2(v.z));
    ffma2(a[3], W, cvt2(v.w));
}

template <int NSTRIP>
__global__ void __launch_bounds__(256)
level_kernel(int cbase, __half* __restrict__ outh) {
    const int d = blockIdx.x;
    const int t = threadIdx.x;

    int cnt = g_cnt[cbase + d];
    if (cnt > CAP) cnt = CAP;
    const int2* bp = g_bpack + (size_t)(cbase + d) * CAP;

    const int c0 = (NSTRIP == 2) ? t * 8 : blockIdx.y * 2048 + t * 8;
    const __half* __restrict__ nvTh = g_nvTh;

    u64 acc[NSTRIP][4];
#pragma unroll
    for (int s = 0; s < NSTRIP; s++)
#pragma unroll
        for (int j = 0; j < 4; j++) acc[s][j] = 0;

    int e = 0;
    for (; e + 4 <= cnt; e += 4) {
        int4 m0 = *reinterpret_cast<const int4*>(bp + e);       // s0,w0,s1,w1
        int4 m1 = *reinterpret_cast<const int4*>(bp + e + 2);   // s2,w2,s3,w3
        const __half* r0 = nvTh + (size_t)m0.x * B_ + c0;
        const __half* r1 = nvTh + (size_t)m0.z * B_ + c0;
        const __half* r2 = nvTh + (size_t)m1.x * B_ + c0;
        const __half* r3 = nvTh + (size_t)m1.z * B_ + c0;
        uint4 v[4][NSTRIP];
#pragma unroll
        for (int s = 0; s < NSTRIP; s++) {
            v[0][s] = ldg_el(r0 + s * 2048);
            v[1][s] = ldg_el(r1 + s * 2048);
            v[2][s] = ldg_el(r2 + s * 2048);
            v[3][s] = ldg_el(r3 + s * 2048);
        }
        u64 W0 = pack2(__int_as_float(m0.y), __int_as_float(m0.y));
        u64 W1 = pack2(__int_as_float(m0.w), __int_as_float(m0.w));
        u64 W2 = pack2(__int_as_float(m1.y), __int_as_float(m1.y));
        u64 W3 = pack2(__int_as_float(m1.w), __int_as_float(m1.w));
#pragma unroll
        for (int s = 0; s < NSTRIP; s++) {
            strip_fma(acc[s], W0, v[0][s]);
            strip_fma(acc[s], W1, v[1][s]);
            strip_fma(acc[s], W2, v[2][s]);
            strip_fma(acc[s], W3, v[3][s]);
        }
    }
    for (; e < cnt; e++) {
        int2 ep = bp[e];
        const __half* r0 = nvTh + (size_t)ep.x * B_ + c0;
        u64 W0 = pack2(__int_as_float(ep.y), __int_as_float(ep.y));
#pragma unroll
        for (int s = 0; s < NSTRIP; s++) {
            uint4 v0 = ldg_el(r0 + s * 2048);
            strip_fma(acc[s], W0, v0);
        }
    }

    // ---- relu + fp16 store ----
#pragma unroll
    for (int s = 0; s < NSTRIP; s++) {
        float r[8];
#pragma unroll
        for (int j = 0; j < 4; j++) {
            float2 f = unpack2(acc[s][j]);
            r[2 * j]     = fmaxf(f.x, 0.f);
            r[2 * j + 1] = fmaxf(f.y, 0.f);
        }
        const int cc = c0 + s * 2048;
        uint4 o; __half2 h;
        h = __floats2half2_rn(r[0], r[1]); o.x = *reinterpret_cast<uint32_t*>(&h);
        h = __floats2half2_rn(r[2], r[3]); o.y = *reinterpret_cast<uint32_t*>(&h);
        h = __floats2half2_rn(r[4], r[5]); o.z = *reinterpret_cast<uint32_t*>(&h);
        h = __floats2half2_rn(r[6], r[7]); o.w = *reinterpret_cast<uint32_t*>(&h);
        *reinterpret_cast<uint4*>(outh + (size_t)d * B_ + cc) = o;
    }
}

// ---------------- launch ----------------
extern "C" void kernel_launch(void* const* d_in, const int* in_sizes, int n_in,
                              void* d_out, int out_size) {
    const float* x    = (const float*)d_in[0];
    const int*   src0 = (const int*)  d_in[1];
    const int*   dst0 = (const int*)  d_in[2];
    const float* w0   = (const float*)d_in[3];
    const int*   src1 = (const int*)  d_in[4];
    const int*   dst1 = (const int*)  d_in[5];
    const float* w1   = (const float*)d_in[6];
    const int*   src2 = (const int*)  d_in[7];
    const int*   dst2 = (const int*)  d_in[8];
    const float* w2   = (const float*)d_in[9];
    float* out = (float*)d_out;

    __half* pnvTh;  cudaGetSymbolAddress((void**)&pnvTh,  g_nvTh);
    __half* poutTh; cudaGetSymbolAddress((void**)&poutTh, g_outTh);

    const int E1 = in_sizes[1], E2 = in_sizes[4], E3 = in_sizes[7];
    const int Etot = E1 + E2 + E3;

    // 1) fused setup: vectorized x transpose + bucket build
    {
        int bucketBlocks = (Etot / 2 + 255) / 256;   // 2 edges/thread
        setup_kernel<<<TBLOCKS + bucketBlocks, 256>>>(
            x, src0, dst0, w0, E1, src1, dst1, w1, E2, src2, dst2, w2, E3);
    }

    // 2) sparse levels (R13 shapes)
    level_kernel<2><<<H1, 256>>>(0,  pnvTh + (size_t)N_IN * B_);
    level_kernel<2><<<H2, 256>>>(H1, pnvTh + (size_t)(N_IN + H1) * B_);
    level_kernel<1><<<dim3(N_OUT, 2), 256>>>(H1 + H2, poutTh);

    // 3) transpose fp16 result to fp32 [B, N_OUT] (+ reset g_cnt for next call)
    transpose_out_kernel<<<dim3(N_OUT / 32, B_ / 32), dim3(32, 8)>>>(out);
}